// round 1
// baseline (speedup 1.0000x reference)
#include <cuda_runtime.h>
#include <cuda_bf16.h>
#include <cstdint>

// Problem constants
#define B_   8
#define D_   512
#define L_   8192
#define ROWS_HG 1024          // stacked fore(0..511) + back(512..1023)

// 256 MiB scratch for hg = [B, 1024, L] fp32 (static device global: allowed)
__device__ float g_hg[(size_t)B_ * ROWS_HG * L_];

// ---------------------------------------------------------------------------
// Kernel A: batched GEMM  hg[b, r, l] = W[r,:] @ x[b,:,l] + bias[r]
//   rows 0..511  -> w_fore/b_fore ; rows 512..1023 -> w_back/b_back
// 128x128 tile, BK=16, 256 threads, 8x8 per thread.
// ---------------------------------------------------------------------------
#define BM 128
#define BN 128
#define BK 16
#define TM 8
#define TN 8

__global__ __launch_bounds__(256, 2)
void mingru_gemm_kernel(const float* __restrict__ x,
                        const float* __restrict__ wf, const float* __restrict__ bf,
                        const float* __restrict__ wb, const float* __restrict__ bb)
{
    const int bcol  = blockIdx.x * BN;       // column base within L
    const int brow  = blockIdx.y * BM;       // row base within 1024
    const int batch = blockIdx.z;

    const float* W;
    const float* bias;
    int wrow;
    if (brow < 512) { W = wf; bias = bf; wrow = brow; }
    else            { W = wb; bias = bb; wrow = brow - 512; }

    const float* X = x + (size_t)batch * D_ * L_;

    __shared__ float As[BK][BM];   // W tile, transposed: As[k][m]
    __shared__ float Bs[BK][BN];   // X tile: Bs[k][c]

    const int tid = threadIdx.x;
    const int tx  = tid & 15;      // n-dim
    const int ty  = tid >> 4;      // m-dim

    float acc[TM][TN];
#pragma unroll
    for (int i = 0; i < TM; i++)
#pragma unroll
        for (int j = 0; j < TN; j++) acc[i][j] = 0.f;

    for (int k0 = 0; k0 < D_; k0 += BK) {
        // --- load W tile: 128 rows x 16 k, transposed into As ---
#pragma unroll
        for (int r = 0; r < 2; r++) {
            int idx = tid + r * 256;          // 0..511
            int m   = idx >> 2;               // 0..127
            int kq  = (idx & 3) * 4;          // 0,4,8,12
            float4 v = *reinterpret_cast<const float4*>(
                &W[(size_t)(wrow + m) * D_ + k0 + kq]);
            As[kq + 0][m] = v.x;
            As[kq + 1][m] = v.y;
            As[kq + 2][m] = v.z;
            As[kq + 3][m] = v.w;
        }
        // --- load X tile: 16 k x 128 cols ---
#pragma unroll
        for (int r = 0; r < 2; r++) {
            int idx = tid + r * 256;
            int kk  = idx >> 5;               // 0..15
            int c   = (idx & 31) * 4;         // 0..124
            *reinterpret_cast<float4*>(&Bs[kk][c]) =
                *reinterpret_cast<const float4*>(
                    &X[(size_t)(k0 + kk) * L_ + bcol + c]);
        }
        __syncthreads();

#pragma unroll
        for (int k = 0; k < BK; k++) {
            float ra[TM], rb[TN];
#pragma unroll
            for (int i = 0; i < TM; i++) ra[i] = As[k][ty * TM + i];
#pragma unroll
            for (int j = 0; j < TN; j++) rb[j] = Bs[k][tx * TN + j];
#pragma unroll
            for (int i = 0; i < TM; i++)
#pragma unroll
                for (int j = 0; j < TN; j++)
                    acc[i][j] = fmaf(ra[i], rb[j], acc[i][j]);
        }
        __syncthreads();
    }

    // --- epilogue: add bias, store to g_hg ---
#pragma unroll
    for (int i = 0; i < TM; i++) {
        int lr = wrow + ty * TM + i;          // row within selected W
        int gr = brow + ty * TM + i;          // row within 1024
        float bv = bias[lr];
        float* outp = g_hg + ((size_t)batch * ROWS_HG + gr) * L_ + bcol + tx * TN;
        float4 v0 = make_float4(acc[i][0] + bv, acc[i][1] + bv,
                                acc[i][2] + bv, acc[i][3] + bv);
        float4 v1 = make_float4(acc[i][4] + bv, acc[i][5] + bv,
                                acc[i][6] + bv, acc[i][7] + bv);
        *reinterpret_cast<float4*>(outp)     = v0;
        *reinterpret_cast<float4*>(outp + 4) = v1;
    }
}

// ---------------------------------------------------------------------------
// Kernel B: per-row linear recurrence  h_t = a_t * h_{t-1} + b_t
//   a = sigmoid(-gate), b = sigmoid(gate) * (h>=0 ? 1+h : exp(h))
// One block (256 threads) per row; 32 contiguous elems per thread.
// Two-pass chunked scan with Hillis-Steele composition scan over summaries.
// Back direction scans right-to-left (flip folded into indexing).
// ---------------------------------------------------------------------------
__device__ __forceinline__ void elem_ab(float h, float g, float& a, float& b)
{
    float em = __expf(-g);                 // e^{-gate}
    float z  = 1.f / (1.f + em);           // sigmoid(gate)
    // a = em/(1+em) = sigmoid(-gate); em=inf -> NaN -> fminf picks 1.0
    a = fminf(em * z, 1.f);
    float gv = (h >= 0.f) ? (1.f + h) : __expf(h);
    b = z * gv;
}

__global__ __launch_bounds__(256)
void mingru_scan_kernel(float* __restrict__ out)
{
    const int row = blockIdx.x;            // 0..4095
    const int b   = row >> 9;              // /512
    const int rem = row & 511;
    const int dir = rem >> 8;              // 0 fore, 1 back
    const int c   = rem & 255;

    const float* hrow = g_hg + ((size_t)b * ROWS_HG + dir * 512 + c) * L_;
    const float* grow = g_hg + ((size_t)b * ROWS_HG + dir * 512 + 256 + c) * L_;
    float* orow = out + ((size_t)b * 512 + dir * 256 + c) * L_;

    const int tid = threadIdx.x;
    const int CH  = L_ / 256;              // 32 elems per thread
    const int s0  = tid * CH;

    __shared__ float sA[256];
    __shared__ float sB[256];

    // ---- pass 1: local chunk composition (A, B) ----
    float A = 1.f, Bc = 0.f;
#pragma unroll 4
    for (int j = 0; j < CH; j++) {
        int s = s0 + j;
        int t = dir ? (L_ - 1 - s) : s;
        float a, bb;
        elem_ab(hrow[t], grow[t], a, bb);
        Bc = fmaf(a, Bc, bb);
        A *= a;
    }
    sA[tid] = A;
    sB[tid] = Bc;
    __syncthreads();

    // ---- inclusive composition scan over 256 chunk summaries ----
    // combine(left, right) = (Al*Ar, Ar*Bl + Br)
    for (int off = 1; off < 256; off <<= 1) {
        float pA = 1.f, pB = 0.f;
        if (tid >= off) { pA = sA[tid - off]; pB = sB[tid - off]; }
        __syncthreads();
        if (tid >= off) {
            float A2 = sA[tid], B2 = sB[tid];
            sA[tid] = pA * A2;
            sB[tid] = fmaf(A2, pB, B2);
        }
        __syncthreads();
    }

    // exclusive prefix = inclusive of previous thread; h before row start = 0
    float h = (tid == 0) ? 0.f : sB[tid - 1];

    // ---- pass 2: recompute, apply prefix, write output ----
#pragma unroll 4
    for (int j = 0; j < CH; j++) {
        int s = s0 + j;
        int t = dir ? (L_ - 1 - s) : s;
        float a, bb;
        elem_ab(hrow[t], grow[t], a, bb);
        h = fmaf(a, h, bb);
        orow[t] = h;
    }
}

// ---------------------------------------------------------------------------
// Launch
// ---------------------------------------------------------------------------
extern "C" void kernel_launch(void* const* d_in, const int* in_sizes, int n_in,
                              void* d_out, int out_size)
{
    const float* x  = (const float*)d_in[0];
    const float* wf = (const float*)d_in[1];
    const float* bf = (const float*)d_in[2];
    const float* wb = (const float*)d_in[3];
    const float* bb = (const float*)d_in[4];
    float* out = (float*)d_out;

    dim3 grid(L_ / BN, ROWS_HG / BM, B_);   // 64 x 8 x 8
    mingru_gemm_kernel<<<grid, 256>>>(x, wf, bf, wb, bb);

    mingru_scan_kernel<<<B_ * 512, 256>>>(out);
}

// round 3
// speedup vs baseline: 1.7478x; 1.7478x over previous
#include <cuda_runtime.h>
#include <cuda_bf16.h>
#include <cstdint>

#define BATCH 8
#define DIM   512
#define LSEQ  8192

// ---------------- device scratch (static globals: allowed) ----------------
__device__ float g_hg[(size_t)BATCH * 1024 * LSEQ];                 // 256 MB
__device__ __nv_bfloat16 g_Wc[1024 * 1024];                         //   2 MB  [row r][k: hi 0..511, lo 512..1023]
__device__ __nv_bfloat16 g_Xb[(size_t)65536 * 1024];                // 128 MB  [n=(b,l)][k: hi, lo]

// ---------------------------------------------------------------------------
// W converter: rows 0..511 = w_fore, 512..1023 = w_back. hi/lo bf16 split.
// ---------------------------------------------------------------------------
__global__ __launch_bounds__(256)
void convert_w(const float* __restrict__ wf, const float* __restrict__ wb)
{
    int idx = blockIdx.x * 256 + threadIdx.x;        // 0..131071
    int r   = idx >> 7;                              // 0..1023
    int dq  = (idx & 127) * 4;                       // 0..508
    const float* src = (r < 512) ? wf + (size_t)r * DIM + dq
                                 : wb + (size_t)(r - 512) * DIM + dq;
    float4 v = *reinterpret_cast<const float4*>(src);
    float vv[4] = {v.x, v.y, v.z, v.w};
    __nv_bfloat16 hi[4], lo[4];
#pragma unroll
    for (int j = 0; j < 4; j++) {
        hi[j] = __float2bfloat16(vv[j]);
        lo[j] = __float2bfloat16(vv[j] - __bfloat162float(hi[j]));
    }
#pragma unroll
    for (int j = 0; j < 4; j++) {
        g_Wc[(size_t)r * 1024 + dq + j]       = hi[j];
        g_Wc[(size_t)r * 1024 + 512 + dq + j] = lo[j];
    }
}

// ---------------------------------------------------------------------------
// X converter: x[b][d][l] f32 -> g_Xb[(b*8192+l)][d] bf16 hi (cols 0..511)
// and lo (cols 512..1023). smem transpose, coalesced both directions.
// Grid: (128 l-chunks of 64, 8 batches), 256 threads.
// ---------------------------------------------------------------------------
__global__ __launch_bounds__(256)
void convert_x(const float* __restrict__ x)
{
    __shared__ float sm[32][65];
    const int b  = blockIdx.y;
    const int l0 = blockIdx.x * 64;
    const float* X = x + (size_t)b * DIM * LSEQ;
    const int tid = threadIdx.x;

    for (int dc = 0; dc < DIM; dc += 32) {
#pragma unroll
        for (int p = 0; p < 8; p++) {
            int d = p * 4 + (tid >> 6);              // 0..31
            int l = tid & 63;
            sm[d][l] = X[(size_t)(dc + d) * LSEQ + l0 + l];
        }
        __syncthreads();

        int l  = tid >> 2;                           // 0..63
        int dq = (tid & 3) * 8;                      // 0,8,16,24
        uint32_t hp[4], lp[4];
#pragma unroll
        for (int j = 0; j < 4; j++) {
            float v0 = sm[dq + 2 * j][l];
            float v1 = sm[dq + 2 * j + 1][l];
            __nv_bfloat16 h0 = __float2bfloat16(v0);
            __nv_bfloat16 h1 = __float2bfloat16(v1);
            __nv_bfloat16 g0 = __float2bfloat16(v0 - __bfloat162float(h0));
            __nv_bfloat16 g1 = __float2bfloat16(v1 - __bfloat162float(h1));
            hp[j] = ((uint32_t)__bfloat16_as_ushort(h1) << 16) | __bfloat16_as_ushort(h0);
            lp[j] = ((uint32_t)__bfloat16_as_ushort(g1) << 16) | __bfloat16_as_ushort(g0);
        }
        size_t rowbase = (size_t)(b * LSEQ + l0 + l) * 1024;
        *reinterpret_cast<uint4*>(&g_Xb[rowbase + dc + dq]) =
            make_uint4(hp[0], hp[1], hp[2], hp[3]);
        *reinterpret_cast<uint4*>(&g_Xb[rowbase + 512 + dc + dq]) =
            make_uint4(lp[0], lp[1], lp[2], lp[3]);
        __syncthreads();
    }
}

// ---------------------------------------------------------------------------
// GEMM via mma.sync.m16n8k16 bf16 (sm_80+ path; tcgen05 not available at the
// harness's PTX target). C[1024 x 65536] = W'[1024 x K'] @ X'[K' x 65536],
// K' = 1536: (hi,hi),(hi,lo),(lo,hi) term blocks of 512 each.
// Block 128x128, BK=32, 8 warps (2m x 4n), warp tile 64x32, double-buffered.
// Grid: (8 m-tiles, 512 n-tiles) -- m fastest so B tiles are shared in L2.
// ---------------------------------------------------------------------------
#define AW 20   // 32-bit words per smem row: 16 data + 4 pad (conflict-free)

__device__ __forceinline__ void mma16816(float* c, const uint32_t* a, const uint32_t* b)
{
    asm volatile(
        "mma.sync.aligned.m16n8k16.row.col.f32.bf16.bf16.f32 "
        "{%0,%1,%2,%3}, {%4,%5,%6,%7}, {%8,%9}, {%0,%1,%2,%3};"
        : "+f"(c[0]), "+f"(c[1]), "+f"(c[2]), "+f"(c[3])
        : "r"(a[0]), "r"(a[1]), "r"(a[2]), "r"(a[3]), "r"(b[0]), "r"(b[1]));
}

__global__ __launch_bounds__(256, 2)
void gemm_hmma(const float* __restrict__ biasf, const float* __restrict__ biasb)
{
    __shared__ uint32_t As[2][128 * AW];
    __shared__ uint32_t Bs[2][128 * AW];

    const int tid  = threadIdx.x;
    const int lane = tid & 31;
    const int wid  = tid >> 5;
    const int mw   = wid & 1;          // 0..1  (64-row m slice)
    const int nw   = wid >> 1;         // 0..3  (32-col n slice)
    const int t4   = lane >> 2;
    const int tm   = lane & 3;

    const int mbase = blockIdx.x * 128;    // 0..896
    const int nbase = blockIdx.y * 128;    // 0..65408

    float acc[4][4][4];
#pragma unroll
    for (int i = 0; i < 4; i++)
#pragma unroll
        for (int j = 0; j < 4; j++)
#pragma unroll
            for (int c = 0; c < 4; c++) acc[i][j][c] = 0.f;

    uint4 ra[2], rb[2];

    // ---- stage tile i into regs ----
    auto ldg = [&](int i) {
        int ka, kb;
        if (i < 16)      { ka = i * 32;              kb = i * 32; }
        else if (i < 32) { ka = (i - 16) * 32;       kb = 512 + (i - 16) * 32; }
        else             { ka = 512 + (i - 32) * 32; kb = (i - 32) * 32; }
#pragma unroll
        for (int j = 0; j < 2; j++) {
            int seg = tid * 2 + j;
            int r   = seg >> 2;
            int sq  = seg & 3;
            ra[j] = *reinterpret_cast<const uint4*>(
                &g_Wc[(size_t)(mbase + r) * 1024 + ka + sq * 8]);
            rb[j] = *reinterpret_cast<const uint4*>(
                &g_Xb[(size_t)(nbase + r) * 1024 + kb + sq * 8]);
        }
    };
    auto sts = [&](int buf) {
#pragma unroll
        for (int j = 0; j < 2; j++) {
            int seg = tid * 2 + j;
            int r   = seg >> 2;
            int sq  = seg & 3;
            uint32_t* pa = &As[buf][r * AW + sq * 4];
            pa[0] = ra[j].x; pa[1] = ra[j].y; pa[2] = ra[j].z; pa[3] = ra[j].w;
            uint32_t* pb = &Bs[buf][r * AW + sq * 4];
            pb[0] = rb[j].x; pb[1] = rb[j].y; pb[2] = rb[j].z; pb[3] = rb[j].w;
        }
    };
    auto compute = [&](int buf) {
#pragma unroll
        for (int ks = 0; ks < 2; ks++) {
            uint32_t af[4][4];
#pragma unroll
            for (int mt = 0; mt < 4; mt++) {
                int row = mw * 64 + mt * 16 + t4;
                int cw  = tm + ks * 8;
                af[mt][0] = As[buf][row * AW + cw];
                af[mt][1] = As[buf][(row + 8) * AW + cw];
                af[mt][2] = As[buf][row * AW + cw + 4];
                af[mt][3] = As[buf][(row + 8) * AW + cw + 4];
            }
            uint32_t bfr[4][2];
#pragma unroll
            for (int nt = 0; nt < 4; nt++) {
                int n  = nw * 32 + nt * 8 + t4;
                int cw = tm + ks * 8;
                bfr[nt][0] = Bs[buf][n * AW + cw];
                bfr[nt][1] = Bs[buf][n * AW + cw + 4];
            }
#pragma unroll
            for (int mt = 0; mt < 4; mt++)
#pragma unroll
                for (int nt = 0; nt < 4; nt++)
                    mma16816(acc[mt][nt], af[mt], bfr[nt]);
        }
    };

    ldg(0);
    sts(0);
    __syncthreads();

    for (int i = 0; i < 48; i++) {
        int cur = i & 1;
        if (i + 1 < 48) ldg(i + 1);
        compute(cur);
        if (i + 1 < 48) {
            sts(cur ^ 1);
            __syncthreads();
        }
    }

    // ---- epilogue: bias + direct store to g_hg ----
    const int b  = nbase >> 13;
    const int l0 = nbase & 8191;
#pragma unroll
    for (int mt = 0; mt < 4; mt++) {
        int r0 = mbase + mw * 64 + mt * 16 + t4;
        int r1 = r0 + 8;
        float b0 = (r0 < 512) ? biasf[r0] : biasb[r0 - 512];
        float b1 = (r1 < 512) ? biasf[r1] : biasb[r1 - 512];
#pragma unroll
        for (int nt = 0; nt < 4; nt++) {
            int l = l0 + nw * 32 + nt * 8 + tm * 2;
            float2 v0 = make_float2(acc[mt][nt][0] + b0, acc[mt][nt][1] + b0);
            float2 v1 = make_float2(acc[mt][nt][2] + b1, acc[mt][nt][3] + b1);
            *reinterpret_cast<float2*>(&g_hg[((size_t)b * 1024 + r0) * LSEQ + l]) = v0;
            *reinterpret_cast<float2*>(&g_hg[((size_t)b * 1024 + r1) * LSEQ + l]) = v1;
        }
    }
}

// ---------------------------------------------------------------------------
// Scan: h_t = a_t h_{t-1} + b_t per row; a = sigmoid(-g), b = sigmoid(g)*g(h).
// Single-pass, smem-staged (257-stride, conflict-free), fully coalesced I/O.
// One block (256 threads) per row. Back direction scans right-to-left.
// ---------------------------------------------------------------------------
__global__ __launch_bounds__(256)
void mingru_scan2(float* __restrict__ out)
{
    extern __shared__ float sm[];              // sa[8224] + sb[8224]
    float* sa = sm;
    float* sb = sm + 8224;
    __shared__ float cA[256], cB[256];

    const int row = blockIdx.x;                // 0..4095
    const int b   = row >> 9;
    const int rem = row & 511;
    const int dir = rem >> 8;
    const int c   = rem & 255;

    const float* hrow = g_hg + ((size_t)b * 1024 + dir * 512 + c) * LSEQ;
    const float* grow = g_hg + ((size_t)b * 1024 + dir * 512 + 256 + c) * LSEQ;
    float* orow = out + ((size_t)b * 512 + dir * 256 + c) * LSEQ;

    const int tid = threadIdx.x;

#pragma unroll 4
    for (int ch = 0; ch < 32; ch++) {
        int e = ch * 256 + tid;
        int t = dir ? (LSEQ - 1 - e) : e;
        float h = hrow[t], g = grow[t];
        float em = __expf(-g);
        float z  = 1.f / (1.f + em);
        float a  = fminf(em * z, 1.f);          // sigmoid(-g); inf*0=NaN -> 1
        float gv = (h >= 0.f) ? (1.f + h) : __expf(h);
        float bv = z * gv;
        int idx = (e & 31) * 257 + (e >> 5);
        sa[idx] = a;
        sb[idx] = bv;
    }
    __syncthreads();

    float A = 1.f, Bc = 0.f;
#pragma unroll
    for (int j = 0; j < 32; j++) {
        float a = sa[j * 257 + tid], bv = sb[j * 257 + tid];
        Bc = fmaf(a, Bc, bv);
        A *= a;
    }
    cA[tid] = A; cB[tid] = Bc;
    __syncthreads();

    for (int off = 1; off < 256; off <<= 1) {
        float pA = 1.f, pB = 0.f;
        if (tid >= off) { pA = cA[tid - off]; pB = cB[tid - off]; }
        __syncthreads();
        if (tid >= off) {
            float A2 = cA[tid], B2 = cB[tid];
            cA[tid] = pA * A2;
            cB[tid] = fmaf(A2, pB, B2);
        }
        __syncthreads();
    }

    float h = (tid == 0) ? 0.f : cB[tid - 1];
#pragma unroll
    for (int j = 0; j < 32; j++) {
        int idx = j * 257 + tid;
        h = fmaf(sa[idx], h, sb[idx]);
        sa[idx] = h;
    }
    __syncthreads();

#pragma unroll 4
    for (int ch = 0; ch < 32; ch++) {
        int e = ch * 256 + tid;
        int t = dir ? (LSEQ - 1 - e) : e;
        orow[t] = sa[(e & 31) * 257 + (e >> 5)];
    }
}

// ---------------------------------------------------------------------------
// Launch
// ---------------------------------------------------------------------------
extern "C" void kernel_launch(void* const* d_in, const int* in_sizes, int n_in,
                              void* d_out, int out_size)
{
    const float* x  = (const float*)d_in[0];
    const float* wf = (const float*)d_in[1];
    const float* bf = (const float*)d_in[2];
    const float* wb = (const float*)d_in[3];
    const float* bb = (const float*)d_in[4];
    float* out = (float*)d_out;

    cudaFuncSetAttribute(mingru_scan2,
                         cudaFuncAttributeMaxDynamicSharedMemorySize, 65792);

    convert_w<<<512, 256>>>(wf, wb);
    convert_x<<<dim3(128, 8), 256>>>(x);

    gemm_hmma<<<dim3(8, 512), 256>>>(bf, bb);

    mingru_scan2<<<4096, 256, 65792>>>(out);
}

// round 4
// speedup vs baseline: 1.7501x; 1.0013x over previous
#include <cuda_runtime.h>
#include <cuda_bf16.h>
#include <cstdint>

#define BATCH 8
#define DIM   512
#define LSEQ  8192

// ---------------- device scratch (static globals: allowed) ----------------
__device__ float g_hg[(size_t)BATCH * 1024 * LSEQ];                 // 256 MB
__device__ __nv_bfloat16 g_Wc[1024 * 1024];                         //   2 MB  [row r][k: hi 0..511, lo 512..1023]
__device__ __nv_bfloat16 g_Xb[(size_t)65536 * 1024];                // 128 MB  [n=(b,l)][k: hi, lo]

// ---------------------------------------------------------------------------
// W converter: rows 0..511 = w_fore, 512..1023 = w_back. hi/lo bf16 split.
// ---------------------------------------------------------------------------
__global__ __launch_bounds__(256)
void convert_w(const float* __restrict__ wf, const float* __restrict__ wb)
{
    int idx = blockIdx.x * 256 + threadIdx.x;        // 0..131071
    int r   = idx >> 7;                              // 0..1023
    int dq  = (idx & 127) * 4;                       // 0..508
    const float* src = (r < 512) ? wf + (size_t)r * DIM + dq
                                 : wb + (size_t)(r - 512) * DIM + dq;
    float4 v = *reinterpret_cast<const float4*>(src);
    float vv[4] = {v.x, v.y, v.z, v.w};
    __nv_bfloat16 hi[4], lo[4];
#pragma unroll
    for (int j = 0; j < 4; j++) {
        hi[j] = __float2bfloat16(vv[j]);
        lo[j] = __float2bfloat16(vv[j] - __bfloat162float(hi[j]));
    }
#pragma unroll
    for (int j = 0; j < 4; j++) {
        g_Wc[(size_t)r * 1024 + dq + j]       = hi[j];
        g_Wc[(size_t)r * 1024 + 512 + dq + j] = lo[j];
    }
}

// ---------------------------------------------------------------------------
// X converter: x[b][d][l] f32 -> g_Xb[(b*8192+l)][d] bf16 hi (cols 0..511)
// and lo (cols 512..1023). smem transpose, coalesced both directions.
// Grid: (128 l-chunks of 64, 8 batches), 256 threads.
// ---------------------------------------------------------------------------
__global__ __launch_bounds__(256)
void convert_x(const float* __restrict__ x)
{
    __shared__ float sm[32][65];
    const int b  = blockIdx.y;
    const int l0 = blockIdx.x * 64;
    const float* X = x + (size_t)b * DIM * LSEQ;
    const int tid = threadIdx.x;

    for (int dc = 0; dc < DIM; dc += 32) {
#pragma unroll
        for (int p = 0; p < 8; p++) {
            int d = p * 4 + (tid >> 6);              // 0..31
            int l = tid & 63;
            sm[d][l] = X[(size_t)(dc + d) * LSEQ + l0 + l];
        }
        __syncthreads();

        int l  = tid >> 2;                           // 0..63
        int dq = (tid & 3) * 8;                      // 0,8,16,24
        uint32_t hp[4], lp[4];
#pragma unroll
        for (int j = 0; j < 4; j++) {
            float v0 = sm[dq + 2 * j][l];
            float v1 = sm[dq + 2 * j + 1][l];
            __nv_bfloat16 h0 = __float2bfloat16(v0);
            __nv_bfloat16 h1 = __float2bfloat16(v1);
            __nv_bfloat16 g0 = __float2bfloat16(v0 - __bfloat162float(h0));
            __nv_bfloat16 g1 = __float2bfloat16(v1 - __bfloat162float(h1));
            hp[j] = ((uint32_t)__bfloat16_as_ushort(h1) << 16) | __bfloat16_as_ushort(h0);
            lp[j] = ((uint32_t)__bfloat16_as_ushort(g1) << 16) | __bfloat16_as_ushort(g0);
        }
        size_t rowbase = (size_t)(b * LSEQ + l0 + l) * 1024;
        *reinterpret_cast<uint4*>(&g_Xb[rowbase + dc + dq]) =
            make_uint4(hp[0], hp[1], hp[2], hp[3]);
        *reinterpret_cast<uint4*>(&g_Xb[rowbase + 512 + dc + dq]) =
            make_uint4(lp[0], lp[1], lp[2], lp[3]);
        __syncthreads();
    }
}

// ---------------------------------------------------------------------------
// GEMM via mma.sync.m16n8k16 bf16 (sm_80+ path; tcgen05 not available at the
// harness's PTX target). C[1024 x 65536] = W'[1024 x K'] @ X'[K' x 65536],
// K' = 1536: (hi,hi),(hi,lo),(lo,hi) term blocks of 512 each.
// Block 128x128, BK=32, 8 warps (2m x 4n), warp tile 64x32, double-buffered.
// Grid: (8 m-tiles, 512 n-tiles) -- m fastest so B tiles are shared in L2.
// ---------------------------------------------------------------------------
#define AW 20   // 32-bit words per smem row: 16 data + 4 pad (conflict-free)

__device__ __forceinline__ void mma16816(float* c, const uint32_t* a, const uint32_t* b)
{
    asm volatile(
        "mma.sync.aligned.m16n8k16.row.col.f32.bf16.bf16.f32 "
        "{%0,%1,%2,%3}, {%4,%5,%6,%7}, {%8,%9}, {%0,%1,%2,%3};"
        : "+f"(c[0]), "+f"(c[1]), "+f"(c[2]), "+f"(c[3])
        : "r"(a[0]), "r"(a[1]), "r"(a[2]), "r"(a[3]), "r"(b[0]), "r"(b[1]));
}

__global__ __launch_bounds__(256, 2)
void gemm_hmma(const float* __restrict__ biasf, const float* __restrict__ biasb)
{
    __shared__ uint32_t As[2][128 * AW];
    __shared__ uint32_t Bs[2][128 * AW];

    const int tid  = threadIdx.x;
    const int lane = tid & 31;
    const int wid  = tid >> 5;
    const int mw   = wid & 1;          // 0..1  (64-row m slice)
    const int nw   = wid >> 1;         // 0..3  (32-col n slice)
    const int t4   = lane >> 2;
    const int tm   = lane & 3;

    const int mbase = blockIdx.x * 128;    // 0..896
    const int nbase = blockIdx.y * 128;    // 0..65408

    float acc[4][4][4];
#pragma unroll
    for (int i = 0; i < 4; i++)
#pragma unroll
        for (int j = 0; j < 4; j++)
#pragma unroll
            for (int c = 0; c < 4; c++) acc[i][j][c] = 0.f;

    uint4 ra[2], rb[2];

    // ---- stage tile i into regs ----
    auto ldg = [&](int i) {
        int ka, kb;
        if (i < 16)      { ka = i * 32;              kb = i * 32; }
        else if (i < 32) { ka = (i - 16) * 32;       kb = 512 + (i - 16) * 32; }
        else             { ka = 512 + (i - 32) * 32; kb = (i - 32) * 32; }
#pragma unroll
        for (int j = 0; j < 2; j++) {
            int seg = tid * 2 + j;
            int r   = seg >> 2;
            int sq  = seg & 3;
            ra[j] = *reinterpret_cast<const uint4*>(
                &g_Wc[(size_t)(mbase + r) * 1024 + ka + sq * 8]);
            rb[j] = *reinterpret_cast<const uint4*>(
                &g_Xb[(size_t)(nbase + r) * 1024 + kb + sq * 8]);
        }
    };
    auto sts = [&](int buf) {
#pragma unroll
        for (int j = 0; j < 2; j++) {
            int seg = tid * 2 + j;
            int r   = seg >> 2;
            int sq  = seg & 3;
            uint32_t* pa = &As[buf][r * AW + sq * 4];
            pa[0] = ra[j].x; pa[1] = ra[j].y; pa[2] = ra[j].z; pa[3] = ra[j].w;
            uint32_t* pb = &Bs[buf][r * AW + sq * 4];
            pb[0] = rb[j].x; pb[1] = rb[j].y; pb[2] = rb[j].z; pb[3] = rb[j].w;
        }
    };
    auto compute = [&](int buf) {
#pragma unroll
        for (int ks = 0; ks < 2; ks++) {
            uint32_t af[4][4];
#pragma unroll
            for (int mt = 0; mt < 4; mt++) {
                int row = mw * 64 + mt * 16 + t4;
                int cw  = tm + ks * 8;
                af[mt][0] = As[buf][row * AW + cw];
                af[mt][1] = As[buf][(row + 8) * AW + cw];
                af[mt][2] = As[buf][row * AW + cw + 4];
                af[mt][3] = As[buf][(row + 8) * AW + cw + 4];
            }
            uint32_t bfr[4][2];
#pragma unroll
            for (int nt = 0; nt < 4; nt++) {
                int n  = nw * 32 + nt * 8 + t4;
                int cw = tm + ks * 8;
                bfr[nt][0] = Bs[buf][n * AW + cw];
                bfr[nt][1] = Bs[buf][n * AW + cw + 4];
            }
#pragma unroll
            for (int mt = 0; mt < 4; mt++)
#pragma unroll
                for (int nt = 0; nt < 4; nt++)
                    mma16816(acc[mt][nt], af[mt], bfr[nt]);
        }
    };

    ldg(0);
    sts(0);
    __syncthreads();

    for (int i = 0; i < 48; i++) {
        int cur = i & 1;
        if (i + 1 < 48) ldg(i + 1);
        compute(cur);
        if (i + 1 < 48) {
            sts(cur ^ 1);
            __syncthreads();
        }
    }

    // ---- epilogue: bias + direct store to g_hg ----
    const int b  = nbase >> 13;
    const int l0 = nbase & 8191;
#pragma unroll
    for (int mt = 0; mt < 4; mt++) {
        int r0 = mbase + mw * 64 + mt * 16 + t4;
        int r1 = r0 + 8;
        float b0 = (r0 < 512) ? biasf[r0] : biasb[r0 - 512];
        float b1 = (r1 < 512) ? biasf[r1] : biasb[r1 - 512];
#pragma unroll
        for (int nt = 0; nt < 4; nt++) {
            int l = l0 + nw * 32 + nt * 8 + tm * 2;
            float2 v0 = make_float2(acc[mt][nt][0] + b0, acc[mt][nt][1] + b0);
            float2 v1 = make_float2(acc[mt][nt][2] + b1, acc[mt][nt][3] + b1);
            *reinterpret_cast<float2*>(&g_hg[((size_t)b * 1024 + r0) * LSEQ + l]) = v0;
            *reinterpret_cast<float2*>(&g_hg[((size_t)b * 1024 + r1) * LSEQ + l]) = v1;
        }
    }
}

// ---------------------------------------------------------------------------
// Scan: h_t = a_t h_{t-1} + b_t per row; a = sigmoid(-g), b = sigmoid(g)*g(h).
// Single-pass, smem-staged (257-stride, conflict-free), fully coalesced I/O.
// One block (256 threads) per row. Back direction scans right-to-left.
// ---------------------------------------------------------------------------
__global__ __launch_bounds__(256)
void mingru_scan2(float* __restrict__ out)
{
    extern __shared__ float sm[];              // sa[8224] + sb[8224]
    float* sa = sm;
    float* sb = sm + 8224;
    __shared__ float cA[256], cB[256];

    const int row = blockIdx.x;                // 0..4095
    const int b   = row >> 9;
    const int rem = row & 511;
    const int dir = rem >> 8;
    const int c   = rem & 255;

    const float* hrow = g_hg + ((size_t)b * 1024 + dir * 512 + c) * LSEQ;
    const float* grow = g_hg + ((size_t)b * 1024 + dir * 512 + 256 + c) * LSEQ;
    float* orow = out + ((size_t)b * 512 + dir * 256 + c) * LSEQ;

    const int tid = threadIdx.x;

#pragma unroll 4
    for (int ch = 0; ch < 32; ch++) {
        int e = ch * 256 + tid;
        int t = dir ? (LSEQ - 1 - e) : e;
        float h = hrow[t], g = grow[t];
        float em = __expf(-g);
        float z  = 1.f / (1.f + em);
        float a  = fminf(em * z, 1.f);          // sigmoid(-g); inf*0=NaN -> 1
        float gv = (h >= 0.f) ? (1.f + h) : __expf(h);
        float bv = z * gv;
        int idx = (e & 31) * 257 + (e >> 5);
        sa[idx] = a;
        sb[idx] = bv;
    }
    __syncthreads();

    float A = 1.f, Bc = 0.f;
#pragma unroll
    for (int j = 0; j < 32; j++) {
        float a = sa[j * 257 + tid], bv = sb[j * 257 + tid];
        Bc = fmaf(a, Bc, bv);
        A *= a;
    }
    cA[tid] = A; cB[tid] = Bc;
    __syncthreads();

    for (int off = 1; off < 256; off <<= 1) {
        float pA = 1.f, pB = 0.f;
        if (tid >= off) { pA = cA[tid - off]; pB = cB[tid - off]; }
        __syncthreads();
        if (tid >= off) {
            float A2 = cA[tid], B2 = cB[tid];
            cA[tid] = pA * A2;
            cB[tid] = fmaf(A2, pB, B2);
        }
        __syncthreads();
    }

    float h = (tid == 0) ? 0.f : cB[tid - 1];
#pragma unroll
    for (int j = 0; j < 32; j++) {
        int idx = j * 257 + tid;
        h = fmaf(sa[idx], h, sb[idx]);
        sa[idx] = h;
    }
    __syncthreads();

#pragma unroll 4
    for (int ch = 0; ch < 32; ch++) {
        int e = ch * 256 + tid;
        int t = dir ? (LSEQ - 1 - e) : e;
        orow[t] = sa[(e & 31) * 257 + (e >> 5)];
    }
}

// ---------------------------------------------------------------------------
// Launch
// ---------------------------------------------------------------------------
extern "C" void kernel_launch(void* const* d_in, const int* in_sizes, int n_in,
                              void* d_out, int out_size)
{
    const float* x  = (const float*)d_in[0];
    const float* wf = (const float*)d_in[1];
    const float* bf = (const float*)d_in[2];
    const float* wb = (const float*)d_in[3];
    const float* bb = (const float*)d_in[4];
    float* out = (float*)d_out;

    cudaFuncSetAttribute(mingru_scan2,
                         cudaFuncAttributeMaxDynamicSharedMemorySize, 65792);

    convert_w<<<512, 256>>>(wf, wb);
    convert_x<<<dim3(128, 8), 256>>>(x);

    gemm_hmma<<<dim3(8, 512), 256>>>(bf, bb);

    mingru_scan2<<<4096, 256, 65792>>>(out);
}

// round 6
// speedup vs baseline: 2.3968x; 1.3696x over previous
#include <cuda_runtime.h>
#include <cuda_bf16.h>
#include <cstdint>

#define BATCH 8
#define DIM   512
#define LSEQ  8192

// ---------------- device scratch (static globals: allowed) ----------------
// W' reordered: row r -> channel ch=8*(r>>4)+(r&7), gate=(r>>3)&1.
// Row layout: [hi 0..511 | lo 512..1023] bf16.
__device__ __nv_bfloat16 g_Wc[1024 * 1024];                 //   2 MB
__device__ __nv_bfloat16 g_Xb[(size_t)65536 * 1024];        // 128 MB [n=(b,l)][hi|lo]
__device__ float g_A[(size_t)BATCH * 512 * LSEQ];           // 128 MB  a coefficients
__device__ float g_B[(size_t)BATCH * 512 * LSEQ];           // 128 MB  b coefficients

__device__ __forceinline__ uint32_t smem_u32(const void* p) {
    uint32_t a;
    asm("{ .reg .u64 t; cvta.to.shared.u64 t, %1; cvt.u32.u64 %0, t; }"
        : "=r"(a) : "l"(p));
    return a;
}
__device__ __forceinline__ void ldsm4(uint32_t* d, uint32_t addr) {
    asm volatile("ldmatrix.sync.aligned.m8n8.x4.shared.b16 {%0,%1,%2,%3}, [%4];"
                 : "=r"(d[0]), "=r"(d[1]), "=r"(d[2]), "=r"(d[3]) : "r"(addr));
}
__device__ __forceinline__ void mma16816(float* c, const uint32_t* a,
                                         uint32_t b0, uint32_t b1) {
    asm volatile(
        "mma.sync.aligned.m16n8k16.row.col.f32.bf16.bf16.f32 "
        "{%0,%1,%2,%3}, {%4,%5,%6,%7}, {%8,%9}, {%0,%1,%2,%3};"
        : "+f"(c[0]), "+f"(c[1]), "+f"(c[2]), "+f"(c[3])
        : "r"(a[0]), "r"(a[1]), "r"(a[2]), "r"(a[3]), "r"(b0), "r"(b1));
}

// pointwise: a = sigmoid(-g), b = sigmoid(g) * (h>=0 ? 1+h : exp(h))
__device__ __forceinline__ void ab_elem(float h, float g, float& a, float& b) {
    float em = __expf(-g);
    float z  = __fdividef(1.f, 1.f + em);   // sigmoid(g); em=inf -> z=0
    a = 1.f - z;
    float gv = (h >= 0.f) ? (1.f + h) : __expf(h);
    b = z * gv;
}

// ---------------------------------------------------------------------------
// W converter with fragment-friendly row reordering + hi/lo split.
// ---------------------------------------------------------------------------
__global__ __launch_bounds__(256)
void convert_w(const float* __restrict__ wf, const float* __restrict__ wb)
{
    int idx = blockIdx.x * 256 + threadIdx.x;        // 0..131071
    int r   = idx >> 7;                              // 0..1023
    int dq  = (idx & 127) * 4;                       // 0..508
    int g   = r >> 4, i = r & 15;
    int ch  = (g << 3) + (i & 7);                    // 0..511
    int gate = i >> 3;
    const float* src = (ch < 256)
        ? wf + (size_t)(gate * 256 + ch) * DIM + dq
        : wb + (size_t)(gate * 256 + ch - 256) * DIM + dq;
    float4 v = *reinterpret_cast<const float4*>(src);
    float vv[4] = {v.x, v.y, v.z, v.w};
#pragma unroll
    for (int j = 0; j < 4; j++) {
        __nv_bfloat16 hi = __float2bfloat16(vv[j]);
        __nv_bfloat16 lo = __float2bfloat16(vv[j] - __bfloat162float(hi));
        g_Wc[(size_t)r * 1024 + dq + j]       = hi;
        g_Wc[(size_t)r * 1024 + 512 + dq + j] = lo;
    }
}

// ---------------------------------------------------------------------------
// X converter: x[b][d][l] -> g_Xb[(b*8192+l)][hi|lo] via smem transpose.
// ---------------------------------------------------------------------------
__global__ __launch_bounds__(256)
void convert_x(const float* __restrict__ x)
{
    __shared__ float sm[32][65];
    const int b  = blockIdx.y;
    const int l0 = blockIdx.x * 64;
    const float* X = x + (size_t)b * DIM * LSEQ;
    const int tid = threadIdx.x;

    for (int dc = 0; dc < DIM; dc += 32) {
#pragma unroll
        for (int p = 0; p < 8; p++) {
            int d = p * 4 + (tid >> 6);
            int l = tid & 63;
            sm[d][l] = X[(size_t)(dc + d) * LSEQ + l0 + l];
        }
        __syncthreads();

        int l  = tid >> 2;
        int dq = (tid & 3) * 8;
        uint32_t hp[4], lp[4];
#pragma unroll
        for (int j = 0; j < 4; j++) {
            float v0 = sm[dq + 2 * j][l];
            float v1 = sm[dq + 2 * j + 1][l];
            __nv_bfloat16 h0 = __float2bfloat16(v0);
            __nv_bfloat16 h1 = __float2bfloat16(v1);
            __nv_bfloat16 g0 = __float2bfloat16(v0 - __bfloat162float(h0));
            __nv_bfloat16 g1 = __float2bfloat16(v1 - __bfloat162float(h1));
            hp[j] = ((uint32_t)__bfloat16_as_ushort(h1) << 16) | __bfloat16_as_ushort(h0);
            lp[j] = ((uint32_t)__bfloat16_as_ushort(g1) << 16) | __bfloat16_as_ushort(g0);
        }
        size_t rowbase = (size_t)(b * LSEQ + l0 + l) * 1024;
        *reinterpret_cast<uint4*>(&g_Xb[rowbase + dc + dq]) =
            make_uint4(hp[0], hp[1], hp[2], hp[3]);
        *reinterpret_cast<uint4*>(&g_Xb[rowbase + 512 + dc + dq]) =
            make_uint4(lp[0], lp[1], lp[2], lp[3]);
        __syncthreads();
    }
}

// ---------------------------------------------------------------------------
// GEMM: C[1024 x 65536] = W'[1024 x 1536'] @ X'[1536' x 65536] (hi/lo 3-term),
// cp.async 3-stage pipeline, BK=64, ldmatrix.x4, XOR-swizzled smem,
// fused (a,b) epilogue writing g_A/g_B.
// Block 128x128, 8 warps (2m x 4n), warp tile 64x32. Grid (8 m, 512 n).
// ---------------------------------------------------------------------------
#define STAGE_BYTES 32768     // A 16KB + B 16KB
#define NK 24                 // 24 x BK64 = 1536

__global__ __launch_bounds__(256, 2)
void gemm_hmma2(const float* __restrict__ bf_, const float* __restrict__ bb_)
{
    extern __shared__ __align__(128) unsigned char smraw[];
    const int tid  = threadIdx.x;
    const int lane = tid & 31;
    const int wid  = tid >> 5;
    const int mw   = wid & 1;
    const int nw   = wid >> 1;
    const int mbase = blockIdx.x * 128;
    const int nbase = blockIdx.y * 128;
    const uint32_t smb = smem_u32(smraw);

    float acc[4][4][4];
#pragma unroll
    for (int i = 0; i < 4; i++)
#pragma unroll
        for (int j = 0; j < 4; j++)
#pragma unroll
            for (int c = 0; c < 4; c++) acc[i][j][c] = 0.f;

    auto issue = [&](int i) {
        int ka, kb;
        if (i < 8)       { ka = i * 64;              kb = i * 64; }
        else if (i < 16) { ka = (i - 8) * 64;        kb = 512 + (i - 8) * 64; }
        else             { ka = 512 + (i - 16) * 64; kb = (i - 16) * 64; }
        int buf = i % 3;
        uint32_t sA = smb + buf * STAGE_BYTES;
        uint32_t sB = sA + 16384;
#pragma unroll
        for (int j = 0; j < 4; j++) {
            int q = tid * 4 + j;          // 0..1023
            int r = q >> 3, c = q & 7;
            const void* gA = &g_Wc[(size_t)(mbase + r) * 1024 + ka + c * 8];
            uint32_t dA = sA + r * 128 + ((uint32_t)(c ^ (r & 7)) << 4);
            asm volatile("cp.async.cg.shared.global [%0], [%1], 16;"
                         :: "r"(dA), "l"(gA));
            const void* gB = &g_Xb[(size_t)(nbase + r) * 1024 + kb + c * 8];
            uint32_t dB = sB + r * 128 + ((uint32_t)(c ^ (r & 7)) << 4);
            asm volatile("cp.async.cg.shared.global [%0], [%1], 16;"
                         :: "r"(dB), "l"(gB));
        }
        asm volatile("cp.async.commit_group;");
    };

    issue(0); issue(1); issue(2);

    const int rla = mw * 64 + (lane & 15);   // A smem row (within 128)
    const int rlb = nw * 32 + (lane & 15);   // B smem row
    const int hi  = lane >> 4;               // chunk half selector

    for (int i = 0; i < NK; i++) {
        asm volatile("cp.async.wait_group 2;");
        __syncthreads();
        int buf = i % 3;
        uint32_t sA = smb + buf * STAGE_BYTES;
        uint32_t sB = sA + 16384;
#pragma unroll
        for (int ks = 0; ks < 4; ks++) {
            uint32_t af[4][4], bfr[2][4];
            uint32_t cxa = (uint32_t)((ks * 2 + hi) ^ (rla & 7)) << 4;
            uint32_t cxb = (uint32_t)((ks * 2 + hi) ^ (rlb & 7)) << 4;
#pragma unroll
            for (int mt = 0; mt < 4; mt++)
                ldsm4(af[mt], sA + (uint32_t)(rla + mt * 16) * 128 + cxa);
#pragma unroll
            for (int n2 = 0; n2 < 2; n2++)
                ldsm4(bfr[n2], sB + (uint32_t)(rlb + n2 * 16) * 128 + cxb);
#pragma unroll
            for (int mt = 0; mt < 4; mt++) {
                mma16816(acc[mt][0], af[mt], bfr[0][0], bfr[0][2]);
                mma16816(acc[mt][1], af[mt], bfr[0][1], bfr[0][3]);
                mma16816(acc[mt][2], af[mt], bfr[1][0], bfr[1][2]);
                mma16816(acc[mt][3], af[mt], bfr[1][1], bfr[1][3]);
            }
        }
        __syncthreads();
        if (i + 3 < NK) issue(i + 3);
        else asm volatile("cp.async.commit_group;");
    }

    // ---- fused epilogue: bias + (a,b) + store ----
    const int t4 = lane >> 2, tm = lane & 3;
    const int bt = nbase >> 13;
    const int l0 = nbase & 8191;
#pragma unroll
    for (int mt = 0; mt < 4; mt++) {
        int rh = mbase + mw * 64 + mt * 16 + t4;       // h row (rh&15 < 8)
        int ch = ((rh >> 4) << 3) + (rh & 7);          // channel 0..511
        float bh, bg;
        if (ch < 256) { bh = bf_[ch];       bg = bf_[256 + ch]; }
        else          { bh = bb_[ch - 256]; bg = bb_[ch]; }
        size_t rowoff = ((size_t)bt * 512 + ch) * LSEQ + l0 + nw * 32 + tm * 2;
#pragma unroll
        for (int nt = 0; nt < 4; nt++) {
            float h0 = acc[mt][nt][0] + bh, h1 = acc[mt][nt][1] + bh;
            float g0 = acc[mt][nt][2] + bg, g1 = acc[mt][nt][3] + bg;
            float a0, b0, a1, b1;
            ab_elem(h0, g0, a0, b0);
            ab_elem(h1, g1, a1, b1);
            *reinterpret_cast<float2*>(&g_A[rowoff + nt * 8]) = make_float2(a0, a1);
            *reinterpret_cast<float2*>(&g_B[rowoff + nt * 8]) = make_float2(b0, b1);
        }
    }
}

// ---------------------------------------------------------------------------
// Scan: h_t = a_t h_{t-1} + b_t, MUFU-free. 512 threads/block, one row each.
// smem 513-stride staging (coalesced global I/O, ~conflict-free smem).
// ---------------------------------------------------------------------------
__global__ __launch_bounds__(512)
void mingru_scan3(float* __restrict__ out)
{
    extern __shared__ float sm[];              // sa[8208] + sb[8208]
    float* sa = sm;
    float* sb = sm + 8208;
    __shared__ float cA[512], cB[512];

    const int row = blockIdx.x;                // 0..4095
    const int b   = row >> 9;
    const int ch  = row & 511;
    const int dir = ch >> 8;                   // 0 fore, 1 back

    const float* ar = g_A + ((size_t)b * 512 + ch) * LSEQ;
    const float* br = g_B + ((size_t)b * 512 + ch) * LSEQ;
    float* orow = out + ((size_t)b * 512 + ch) * LSEQ;

    const int tid = threadIdx.x;

#pragma unroll 4
    for (int c2 = 0; c2 < 16; c2++) {
        int e = c2 * 512 + tid;
        int t = dir ? (LSEQ - 1 - e) : e;
        int idx = (e & 15) * 513 + (e >> 4);
        sa[idx] = ar[t];
        sb[idx] = br[t];
    }
    __syncthreads();

    float A = 1.f, Bc = 0.f;
#pragma unroll
    for (int j = 0; j < 16; j++) {
        float a = sa[j * 513 + tid], bv = sb[j * 513 + tid];
        Bc = fmaf(a, Bc, bv);
        A *= a;
    }
    cA[tid] = A; cB[tid] = Bc;
    __syncthreads();

    for (int off = 1; off < 512; off <<= 1) {
        float pA = 1.f, pB = 0.f;
        if (tid >= off) { pA = cA[tid - off]; pB = cB[tid - off]; }
        __syncthreads();
        if (tid >= off) {
            float A2 = cA[tid], B2 = cB[tid];
            cA[tid] = pA * A2;
            cB[tid] = fmaf(A2, pB, B2);
        }
        __syncthreads();
    }

    float h = (tid == 0) ? 0.f : cB[tid - 1];
#pragma unroll
    for (int j = 0; j < 16; j++) {
        int idx = j * 513 + tid;
        h = fmaf(sa[idx], h, sb[idx]);
        sa[idx] = h;
    }
    __syncthreads();

#pragma unroll 4
    for (int c2 = 0; c2 < 16; c2++) {
        int e = c2 * 512 + tid;
        int t = dir ? (LSEQ - 1 - e) : e;
        orow[t] = sa[(e & 15) * 513 + (e >> 4)];
    }
}

// ---------------------------------------------------------------------------
// Launch
// ---------------------------------------------------------------------------
extern "C" void kernel_launch(void* const* d_in, const int* in_sizes, int n_in,
                              void* d_out, int out_size)
{
    const float* x  = (const float*)d_in[0];
    const float* wf = (const float*)d_in[1];
    const float* bf = (const float*)d_in[2];
    const float* wb = (const float*)d_in[3];
    const float* bb = (const float*)d_in[4];
    float* out = (float*)d_out;

    cudaFuncSetAttribute(gemm_hmma2,
                         cudaFuncAttributeMaxDynamicSharedMemorySize,
                         3 * STAGE_BYTES);
    cudaFuncSetAttribute(mingru_scan3,
                         cudaFuncAttributeMaxDynamicSharedMemorySize, 65664);

    convert_w<<<512, 256>>>(wf, wb);
    convert_x<<<dim3(128, 8), 256>>>(x);

    gemm_hmma2<<<dim3(8, 512), 256, 3 * STAGE_BYTES>>>(bf, bb);

    mingru_scan3<<<4096, 512, 65664>>>(out);
}

// round 10
// speedup vs baseline: 3.2221x; 1.3443x over previous
#include <cuda_runtime.h>
#include <cuda_fp16.h>
#include <cstdint>

#define BATCH 8
#define DIM   512
#define LSEQ  8192

// ---------------- device scratch (static globals: allowed) ----------------
// W' (fp16, quantized): row r -> channel ch=8*(r>>4)+(r&7), gate=(r>>3)&1.
__device__ __half g_Wc[1024 * 512];                         //   1 MB
__device__ __half g_Xb[(size_t)65536 * 1024];               // 128 MB [n=(b,l)][xh|xl]
__device__ float g_A[(size_t)BATCH * 512 * LSEQ];           // 128 MB  a coefficients
__device__ float g_B[(size_t)BATCH * 512 * LSEQ];           // 128 MB  b coefficients

__device__ __forceinline__ uint32_t smem_u32(const void* p) {
    uint32_t a;
    asm("{ .reg .u64 t; cvta.to.shared.u64 t, %1; cvt.u32.u64 %0, t; }"
        : "=r"(a) : "l"(p));
    return a;
}
__device__ __forceinline__ void ldsm4(uint32_t* d, uint32_t addr) {
    asm volatile("ldmatrix.sync.aligned.m8n8.x4.shared.b16 {%0,%1,%2,%3}, [%4];"
                 : "=r"(d[0]), "=r"(d[1]), "=r"(d[2]), "=r"(d[3]) : "r"(addr));
}
__device__ __forceinline__ void mma16816(float* c, const uint32_t* a,
                                         uint32_t b0, uint32_t b1) {
    asm volatile(
        "mma.sync.aligned.m16n8k16.row.col.f32.f16.f16.f32 "
        "{%0,%1,%2,%3}, {%4,%5,%6,%7}, {%8,%9}, {%0,%1,%2,%3};"
        : "+f"(c[0]), "+f"(c[1]), "+f"(c[2]), "+f"(c[3])
        : "r"(a[0]), "r"(a[1]), "r"(a[2]), "r"(a[3]), "r"(b0), "r"(b1));
}

// pointwise: a = sigmoid(-g), b = sigmoid(g) * (h>=0 ? 1+h : exp(h))
__device__ __forceinline__ void ab_elem(float h, float g, float& a, float& b) {
    float em = __expf(-g);
    float z  = __fdividef(1.f, 1.f + em);   // sigmoid(g); em=inf -> z=0
    a = 1.f - z;
    float gv = (h >= 0.f) ? (1.f + h) : __expf(h);
    b = z * gv;
}

// ---------------------------------------------------------------------------
// W converter: fragment-friendly row reorder, fp16 quantize (no split).
// ---------------------------------------------------------------------------
__global__ __launch_bounds__(256)
void convert_w(const float* __restrict__ wf, const float* __restrict__ wb)
{
    int idx = blockIdx.x * 256 + threadIdx.x;        // 0..131071
    int r   = idx >> 7;                              // 0..1023
    int dq  = (idx & 127) * 4;                       // 0..508
    int g   = r >> 4, i = r & 15;
    int ch  = (g << 3) + (i & 7);                    // 0..511
    int gate = i >> 3;
    const float* src = (ch < 256)
        ? wf + (size_t)(gate * 256 + ch) * DIM + dq
        : wb + (size_t)(gate * 256 + ch - 256) * DIM + dq;
    float4 v = *reinterpret_cast<const float4*>(src);
    float vv[4] = {v.x, v.y, v.z, v.w};
#pragma unroll
    for (int j = 0; j < 4; j++)
        g_Wc[(size_t)r * 512 + dq + j] = __float2half(vv[j]);
}

// ---------------------------------------------------------------------------
// X converter: x[b][d][l] -> g_Xb[(b*8192+l)][xh | xl] (fp16 hi/lo split)
// via smem transpose, coalesced both directions.
// ---------------------------------------------------------------------------
__global__ __launch_bounds__(256)
void convert_x(const float* __restrict__ x)
{
    __shared__ float sm[32][65];
    const int b  = blockIdx.y;
    const int l0 = blockIdx.x * 64;
    const float* X = x + (size_t)b * DIM * LSEQ;
    const int tid = threadIdx.x;

    for (int dc = 0; dc < DIM; dc += 32) {
#pragma unroll
        for (int p = 0; p < 8; p++) {
            int d = p * 4 + (tid >> 6);
            int l = tid & 63;
            sm[d][l] = X[(size_t)(dc + d) * LSEQ + l0 + l];
        }
        __syncthreads();

        int l  = tid >> 2;
        int dq = (tid & 3) * 8;
        uint32_t hp[4], lp[4];
#pragma unroll
        for (int j = 0; j < 4; j++) {
            float v0 = sm[dq + 2 * j][l];
            float v1 = sm[dq + 2 * j + 1][l];
            __half h0 = __float2half(v0);
            __half h1 = __float2half(v1);
            __half g0 = __float2half(v0 - __half2float(h0));
            __half g1 = __float2half(v1 - __half2float(h1));
            hp[j] = ((uint32_t)__half_as_ushort(h1) << 16) | __half_as_ushort(h0);
            lp[j] = ((uint32_t)__half_as_ushort(g1) << 16) | __half_as_ushort(g0);
        }
        size_t rowbase = (size_t)(b * LSEQ + l0 + l) * 1024;
        *reinterpret_cast<uint4*>(&g_Xb[rowbase + dc + dq]) =
            make_uint4(hp[0], hp[1], hp[2], hp[3]);
        *reinterpret_cast<uint4*>(&g_Xb[rowbase + 512 + dc + dq]) =
            make_uint4(lp[0], lp[1], lp[2], lp[3]);
        __syncthreads();
    }
}

// ---------------------------------------------------------------------------
// GEMM: C[1024 x 65536] = Wh[1024 x 512] @ (Xh + Xl)[512 x 65536], fp16 2-term
// (K' = 1024). cp.async 3-stage, BK=64, ldmatrix.x4, XOR-swizzled smem,
// fused (a,b) epilogue. Block 128x128, 8 warps (2m x 4n). Grid (8 m, 512 n).
// ---------------------------------------------------------------------------
#define STAGE_BYTES 32768     // A 16KB + B 16KB
#define NK 16                 // 16 x BK64 = 1024

__global__ __launch_bounds__(256, 2)
void gemm_hmma2(const float* __restrict__ bf_, const float* __restrict__ bb_)
{
    extern __shared__ __align__(128) unsigned char smraw[];
    const int tid  = threadIdx.x;
    const int lane = tid & 31;
    const int wid  = tid >> 5;
    const int mw   = wid & 1;
    const int nw   = wid >> 1;
    const int mbase = blockIdx.x * 128;
    const int nbase = blockIdx.y * 128;
    const uint32_t smb = smem_u32(smraw);

    float acc[4][4][4];
#pragma unroll
    for (int i = 0; i < 4; i++)
#pragma unroll
        for (int j = 0; j < 4; j++)
#pragma unroll
            for (int c = 0; c < 4; c++) acc[i][j][c] = 0.f;

    auto issue = [&](int i) {
        int ka, kb;
        if (i < 8) { ka = i * 64;       kb = i * 64; }
        else       { ka = (i - 8) * 64; kb = 512 + (i - 8) * 64; }
        int buf = i % 3;
        uint32_t sA = smb + buf * STAGE_BYTES;
        uint32_t sB = sA + 16384;
#pragma unroll
        for (int j = 0; j < 4; j++) {
            int q = tid * 4 + j;          // 0..1023
            int r = q >> 3, c = q & 7;
            const void* gA = &g_Wc[(size_t)(mbase + r) * 512 + ka + c * 8];
            uint32_t dA = sA + r * 128 + ((uint32_t)(c ^ (r & 7)) << 4);
            asm volatile("cp.async.cg.shared.global [%0], [%1], 16;"
                         :: "r"(dA), "l"(gA));
            const void* gB = &g_Xb[(size_t)(nbase + r) * 1024 + kb + c * 8];
            uint32_t dB = sB + r * 128 + ((uint32_t)(c ^ (r & 7)) << 4);
            asm volatile("cp.async.cg.shared.global [%0], [%1], 16;"
                         :: "r"(dB), "l"(gB));
        }
        asm volatile("cp.async.commit_group;");
    };

    issue(0); issue(1); issue(2);

    const int rla = mw * 64 + (lane & 15);   // A smem row (within 128)
    const int rlb = nw * 32 + (lane & 15);   // B smem row
    const int hi  = lane >> 4;               // chunk half selector

    for (int i = 0; i < NK; i++) {
        asm volatile("cp.async.wait_group 2;");
        __syncthreads();
        int buf = i % 3;
        uint32_t sA = smb + buf * STAGE_BYTES;
        uint32_t sB = sA + 16384;
#pragma unroll
        for (int ks = 0; ks < 4; ks++) {
            uint32_t af[4][4], bfr[2][4];
            uint32_t cxa = (uint32_t)((ks * 2 + hi) ^ (rla & 7)) << 4;
            uint32_t cxb = (uint32_t)((ks * 2 + hi) ^ (rlb & 7)) << 4;
#pragma unroll
            for (int mt = 0; mt < 4; mt++)
                ldsm4(af[mt], sA + (uint32_t)(rla + mt * 16) * 128 + cxa);
#pragma unroll
            for (int n2 = 0; n2 < 2; n2++)
                ldsm4(bfr[n2], sB + (uint32_t)(rlb + n2 * 16) * 128 + cxb);
#pragma unroll
            for (int mt = 0; mt < 4; mt++) {
                mma16816(acc[mt][0], af[mt], bfr[0][0], bfr[0][2]);
                mma16816(acc[mt][1], af[mt], bfr[0][1], bfr[0][3]);
                mma16816(acc[mt][2], af[mt], bfr[1][0], bfr[1][2]);
                mma16816(acc[mt][3], af[mt], bfr[1][1], bfr[1][3]);
            }
        }
        __syncthreads();
        if (i + 3 < NK) issue(i + 3);
        else asm volatile("cp.async.commit_group;");
    }

    // ---- fused epilogue: bias + (a,b) + store ----
    const int t4 = lane >> 2, tm = lane & 3;
    const int bt = nbase >> 13;
    const int l0 = nbase & 8191;
#pragma unroll
    for (int mt = 0; mt < 4; mt++) {
        int rh = mbase + mw * 64 + mt * 16 + t4;       // h row (rh&15 < 8)
        int ch = ((rh >> 4) << 3) + (rh & 7);          // channel 0..511
        float bh, bg;
        if (ch < 256) { bh = bf_[ch];       bg = bf_[256 + ch]; }
        else          { bh = bb_[ch - 256]; bg = bb_[ch]; }
        size_t rowoff = ((size_t)bt * 512 + ch) * LSEQ + l0 + nw * 32 + tm * 2;
#pragma unroll
        for (int nt = 0; nt < 4; nt++) {
            float h0 = acc[mt][nt][0] + bh, h1 = acc[mt][nt][1] + bh;
            float g0 = acc[mt][nt][2] + bg, g1 = acc[mt][nt][3] + bg;
            float a0, b0, a1, b1;
            ab_elem(h0, g0, a0, b0);
            ab_elem(h1, g1, a1, b1);
            *reinterpret_cast<float2*>(&g_A[rowoff + nt * 8]) = make_float2(a0, a1);
            *reinterpret_cast<float2*>(&g_B[rowoff + nt * 8]) = make_float2(b0, b1);
        }
    }
}

// ---------------------------------------------------------------------------
// Scan: h_t = a_t h_{t-1} + b_t, MUFU-free. 512 threads/block, one row each.
// smem 513-stride staging (coalesced global I/O, ~conflict-free smem).
// ---------------------------------------------------------------------------
__global__ __launch_bounds__(512)
void mingru_scan3(float* __restrict__ out)
{
    extern __shared__ float sm[];              // sa[8208] + sb[8208]
    float* sa = sm;
    float* sb = sm + 8208;
    __shared__ float cA[512], cB[512];

    const int row = blockIdx.x;                // 0..4095
    const int b   = row >> 9;
    const int ch  = row & 511;
    const int dir = ch >> 8;                   // 0 fore, 1 back

    const float* ar = g_A + ((size_t)b * 512 + ch) * LSEQ;
    const float* br = g_B + ((size_t)b * 512 + ch) * LSEQ;
    float* orow = out + ((size_t)b * 512 + ch) * LSEQ;

    const int tid = threadIdx.x;

#pragma unroll 4
    for (int c2 = 0; c2 < 16; c2++) {
        int e = c2 * 512 + tid;
        int t = dir ? (LSEQ - 1 - e) : e;
        int idx = (e & 15) * 513 + (e >> 4);
        sa[idx] = ar[t];
        sb[idx] = br[t];
    }
    __syncthreads();

    float A = 1.f, Bc = 0.f;
#pragma unroll
    for (int j = 0; j < 16; j++) {
        float a = sa[j * 513 + tid], bv = sb[j * 513 + tid];
        Bc = fmaf(a, Bc, bv);
        A *= a;
    }
    cA[tid] = A; cB[tid] = Bc;
    __syncthreads();

    for (int off = 1; off < 512; off <<= 1) {
        float pA = 1.f, pB = 0.f;
        if (tid >= off) { pA = cA[tid - off]; pB = cB[tid - off]; }
        __syncthreads();
        if (tid >= off) {
            float A2 = cA[tid], B2 = cB[tid];
            cA[tid] = pA * A2;
            cB[tid] = fmaf(A2, pB, B2);
        }
        __syncthreads();
    }

    float h = (tid == 0) ? 0.f : cB[tid - 1];
#pragma unroll
    for (int j = 0; j < 16; j++) {
        int idx = j * 513 + tid;
        h = fmaf(sa[idx], h, sb[idx]);
        sa[idx] = h;
    }
    __syncthreads();

#pragma unroll 4
    for (int c2 = 0; c2 < 16; c2++) {
        int e = c2 * 512 + tid;
        int t = dir ? (LSEQ - 1 - e) : e;
        orow[t] = sa[(e & 15) * 513 + (e >> 4)];
    }
}

// ---------------------------------------------------------------------------
// Launch
// ---------------------------------------------------------------------------
extern "C" void kernel_launch(void* const* d_in, const int* in_sizes, int n_in,
                              void* d_out, int out_size)
{
    const float* x  = (const float*)d_in[0];
    const float* wf = (const float*)d_in[1];
    const float* bf = (const float*)d_in[2];
    const float* wb = (const float*)d_in[3];
    const float* bb = (const float*)d_in[4];
    float* out = (float*)d_out;

    cudaFuncSetAttribute(gemm_hmma2,
                         cudaFuncAttributeMaxDynamicSharedMemorySize,
                         3 * STAGE_BYTES);
    cudaFuncSetAttribute(mingru_scan3,
                         cudaFuncAttributeMaxDynamicSharedMemorySize, 65664);

    convert_w<<<512, 256>>>(wf, wb);
    convert_x<<<dim3(128, 8), 256>>>(x);

    gemm_hmma2<<<dim3(8, 512), 256, 3 * STAGE_BYTES>>>(bf, bb);

    mingru_scan3<<<4096, 512, 65664>>>(out);
}

// round 13
// speedup vs baseline: 5.6280x; 1.7467x over previous
#include <cuda_runtime.h>
#include <cuda_fp16.h>
#include <cstdint>

#define BATCH 8
#define DIM   512
#define LSEQ  8192

// ---------------- device scratch (static globals: allowed) ----------------
// W' (fp16): row r -> channel ch=8*(r>>4)+(r&7), gate=(r>>3)&1.
__device__ __half g_Wc[1024 * 512];                         //   1 MB
__device__ __half g_Xb[(size_t)65536 * 512];                //  64 MB [n=(b,l)][k]
__device__ __half2 g_AB[(size_t)BATCH * 512 * LSEQ];        // 128 MB  (a,b) pairs

__device__ __forceinline__ uint32_t smem_u32(const void* p) {
    uint32_t a;
    asm("{ .reg .u64 t; cvta.to.shared.u64 t, %1; cvt.u32.u64 %0, t; }"
        : "=r"(a) : "l"(p));
    return a;
}
__device__ __forceinline__ void ldsm4(uint32_t* d, uint32_t addr) {
    asm volatile("ldmatrix.sync.aligned.m8n8.x4.shared.b16 {%0,%1,%2,%3}, [%4];"
                 : "=r"(d[0]), "=r"(d[1]), "=r"(d[2]), "=r"(d[3]) : "r"(addr));
}
__device__ __forceinline__ void mma16816(float* c, const uint32_t* a,
                                         uint32_t b0, uint32_t b1) {
    asm volatile(
        "mma.sync.aligned.m16n8k16.row.col.f32.f16.f16.f32 "
        "{%0,%1,%2,%3}, {%4,%5,%6,%7}, {%8,%9}, {%0,%1,%2,%3};"
        : "+f"(c[0]), "+f"(c[1]), "+f"(c[2]), "+f"(c[3])
        : "r"(a[0]), "r"(a[1]), "r"(a[2]), "r"(a[3]), "r"(b0), "r"(b1));
}

// pointwise: a = sigmoid(-g), b = sigmoid(g) * (h>=0 ? 1+h : exp(h))
__device__ __forceinline__ void ab_elem(float h, float g, float& a, float& b) {
    float em = __expf(-g);
    float z  = __fdividef(1.f, 1.f + em);   // sigmoid(g); em=inf -> z=0
    a = 1.f - z;
    float gv = (h >= 0.f) ? (1.f + h) : __expf(h);
    b = z * gv;
}

// ---------------------------------------------------------------------------
// W converter: fragment-friendly row reorder, fp16 quantize.
// ---------------------------------------------------------------------------
__global__ __launch_bounds__(256)
void convert_w(const float* __restrict__ wf, const float* __restrict__ wb)
{
    int idx = blockIdx.x * 256 + threadIdx.x;        // 0..131071
    int r   = idx >> 7;                              // 0..1023
    int dq  = (idx & 127) * 4;                       // 0..508
    int g   = r >> 4, i = r & 15;
    int ch  = (g << 3) + (i & 7);                    // 0..511
    int gate = i >> 3;
    const float* src = (ch < 256)
        ? wf + (size_t)(gate * 256 + ch) * DIM + dq
        : wb + (size_t)(gate * 256 + ch - 256) * DIM + dq;
    float4 v = *reinterpret_cast<const float4*>(src);
    float vv[4] = {v.x, v.y, v.z, v.w};
#pragma unroll
    for (int j = 0; j < 4; j++)
        g_Wc[(size_t)r * 512 + dq + j] = __float2half(vv[j]);
}

// ---------------------------------------------------------------------------
// X converter: x[b][d][l] -> g_Xb[(b*8192+l)][d] fp16 via smem transpose.
// ---------------------------------------------------------------------------
__global__ __launch_bounds__(256)
void convert_x(const float* __restrict__ x)
{
    __shared__ float sm[32][65];
    const int b  = blockIdx.y;
    const int l0 = blockIdx.x * 64;
    const float* X = x + (size_t)b * DIM * LSEQ;
    const int tid = threadIdx.x;

    for (int dc = 0; dc < DIM; dc += 32) {
#pragma unroll
        for (int p = 0; p < 8; p++) {
            int d = p * 4 + (tid >> 6);
            int l = tid & 63;
            sm[d][l] = X[(size_t)(dc + d) * LSEQ + l0 + l];
        }
        __syncthreads();

        int l  = tid >> 2;
        int dq = (tid & 3) * 8;
        uint32_t hp[4];
#pragma unroll
        for (int j = 0; j < 4; j++) {
            __half h0 = __float2half(sm[dq + 2 * j][l]);
            __half h1 = __float2half(sm[dq + 2 * j + 1][l]);
            hp[j] = ((uint32_t)__half_as_ushort(h1) << 16) | __half_as_ushort(h0);
        }
        *reinterpret_cast<uint4*>(&g_Xb[(size_t)(b * LSEQ + l0 + l) * 512 + dc + dq]) =
            make_uint4(hp[0], hp[1], hp[2], hp[3]);
        __syncthreads();
    }
}

// ---------------------------------------------------------------------------
// GEMM: C[1024 x 65536] = Wh[1024 x 512] @ Xh[512 x 65536], pure fp16 (K=512).
// cp.async 3-stage, BK=64, ldmatrix.x4, XOR-swizzled smem, fused (a,b)
// epilogue writing half2 pairs. Block 128x128, 8 warps. Grid (8 m, 512 n).
// ---------------------------------------------------------------------------
#define STAGE_BYTES 32768     // A 16KB + B 16KB
#define NK 8                  // 8 x BK64 = 512

__global__ __launch_bounds__(256, 2)
void gemm_hmma2(const float* __restrict__ bf_, const float* __restrict__ bb_)
{
    extern __shared__ __align__(128) unsigned char smraw[];
    const int tid  = threadIdx.x;
    const int lane = tid & 31;
    const int wid  = tid >> 5;
    const int mw   = wid & 1;
    const int nw   = wid >> 1;
    const int mbase = blockIdx.x * 128;
    const int nbase = blockIdx.y * 128;
    const uint32_t smb = smem_u32(smraw);

    float acc[4][4][4];
#pragma unroll
    for (int i = 0; i < 4; i++)
#pragma unroll
        for (int j = 0; j < 4; j++)
#pragma unroll
            for (int c = 0; c < 4; c++) acc[i][j][c] = 0.f;

    auto issue = [&](int i) {
        int k0 = i * 64;
        int buf = i % 3;
        uint32_t sA = smb + buf * STAGE_BYTES;
        uint32_t sB = sA + 16384;
#pragma unroll
        for (int j = 0; j < 4; j++) {
            int q = tid * 4 + j;          // 0..1023
            int r = q >> 3, c = q & 7;
            const void* gA = &g_Wc[(size_t)(mbase + r) * 512 + k0 + c * 8];
            uint32_t dA = sA + r * 128 + ((uint32_t)(c ^ (r & 7)) << 4);
            asm volatile("cp.async.cg.shared.global [%0], [%1], 16;"
                         :: "r"(dA), "l"(gA));
            const void* gB = &g_Xb[(size_t)(nbase + r) * 512 + k0 + c * 8];
            uint32_t dB = sB + r * 128 + ((uint32_t)(c ^ (r & 7)) << 4);
            asm volatile("cp.async.cg.shared.global [%0], [%1], 16;"
                         :: "r"(dB), "l"(gB));
        }
        asm volatile("cp.async.commit_group;");
    };

    issue(0); issue(1); issue(2);

    const int rla = mw * 64 + (lane & 15);   // A smem row (within 128)
    const int rlb = nw * 32 + (lane & 15);   // B smem row
    const int hi  = lane >> 4;               // chunk half selector

    for (int i = 0; i < NK; i++) {
        asm volatile("cp.async.wait_group 2;");
        __syncthreads();
        int buf = i % 3;
        uint32_t sA = smb + buf * STAGE_BYTES;
        uint32_t sB = sA + 16384;
#pragma unroll
        for (int ks = 0; ks < 4; ks++) {
            uint32_t af[4][4], bfr[2][4];
            uint32_t cxa = (uint32_t)((ks * 2 + hi) ^ (rla & 7)) << 4;
            uint32_t cxb = (uint32_t)((ks * 2 + hi) ^ (rlb & 7)) << 4;
#pragma unroll
            for (int mt = 0; mt < 4; mt++)
                ldsm4(af[mt], sA + (uint32_t)(rla + mt * 16) * 128 + cxa);
#pragma unroll
            for (int n2 = 0; n2 < 2; n2++)
                ldsm4(bfr[n2], sB + (uint32_t)(rlb + n2 * 16) * 128 + cxb);
#pragma unroll
            for (int mt = 0; mt < 4; mt++) {
                mma16816(acc[mt][0], af[mt], bfr[0][0], bfr[0][2]);
                mma16816(acc[mt][1], af[mt], bfr[0][1], bfr[0][3]);
                mma16816(acc[mt][2], af[mt], bfr[1][0], bfr[1][2]);
                mma16816(acc[mt][3], af[mt], bfr[1][1], bfr[1][3]);
            }
        }
        __syncthreads();
        if (i + 3 < NK) issue(i + 3);
        else asm volatile("cp.async.commit_group;");
    }

    // ---- fused epilogue: bias + (a,b) + half2 store ----
    const int t4 = lane >> 2, tm = lane & 3;
    const int bt = nbase >> 13;
    const int l0 = nbase & 8191;
#pragma unroll
    for (int mt = 0; mt < 4; mt++) {
        int rh = mbase + mw * 64 + mt * 16 + t4;       // h row (rh&15 < 8)
        int ch = ((rh >> 4) << 3) + (rh & 7);          // channel 0..511
        float bh, bg;
        if (ch < 256) { bh = bf_[ch];       bg = bf_[256 + ch]; }
        else          { bh = bb_[ch - 256]; bg = bb_[ch]; }
        size_t rowoff = ((size_t)bt * 512 + ch) * LSEQ + l0 + nw * 32 + tm * 2;
#pragma unroll
        for (int nt = 0; nt < 4; nt++) {
            float h0 = acc[mt][nt][0] + bh, h1 = acc[mt][nt][1] + bh;
            float g0 = acc[mt][nt][2] + bg, g1 = acc[mt][nt][3] + bg;
            float a0, b0, a1, b1;
            ab_elem(h0, g0, a0, b0);
            ab_elem(h1, g1, a1, b1);
            __half2 p0 = __floats2half2_rn(a0, b0);
            __half2 p1 = __floats2half2_rn(a1, b1);
            *reinterpret_cast<uint2*>(&g_AB[rowoff + nt * 8]) =
                make_uint2(*reinterpret_cast<uint32_t*>(&p0),
                           *reinterpret_cast<uint32_t*>(&p1));
        }
    }
}

// ---------------------------------------------------------------------------
// Scan: h_t = a_t h_{t-1} + b_t. 512 threads/block, one row per block.
// half2 (a,b) input; smem 513-stride staging; coalesced global I/O.
// ---------------------------------------------------------------------------
__global__ __launch_bounds__(512)
void mingru_scan3(float* __restrict__ out)
{
    extern __shared__ float sm[];              // sa[8208] + sb[8208]
    float* sa = sm;
    float* sb = sm + 8208;
    __shared__ float cA[512], cB[512];

    const int row = blockIdx.x;                // 0..4095
    const int b   = row >> 9;
    const int ch  = row & 511;
    const int dir = ch >> 8;                   // 0 fore, 1 back

    const __half2* abr = g_AB + ((size_t)b * 512 + ch) * LSEQ;
    float* orow = out + ((size_t)b * 512 + ch) * LSEQ;

    const int tid = threadIdx.x;

#pragma unroll 4
    for (int c2 = 0; c2 < 16; c2++) {
        int e = c2 * 512 + tid;
        int t = dir ? (LSEQ - 1 - e) : e;
        float2 v = __half22float2(abr[t]);
        int idx = (e & 15) * 513 + (e >> 4);
        sa[idx] = v.x;
        sb[idx] = v.y;
    }
    __syncthreads();

    float A = 1.f, Bc = 0.f;
#pragma unroll
    for (int j = 0; j < 16; j++) {
        float a = sa[j * 513 + tid], bv = sb[j * 513 + tid];
        Bc = fmaf(a, Bc, bv);
        A *= a;
    }
    cA[tid] = A; cB[tid] = Bc;
    __syncthreads();

    for (int off = 1; off < 512; off <<= 1) {
        float pA = 1.f, pB = 0.f;
        if (tid >= off) { pA = cA[tid - off]; pB = cB[tid - off]; }
        __syncthreads();
        if (tid >= off) {
            float A2 = cA[tid], B2 = cB[tid];
            cA[tid] = pA * A2;
            cB[tid] = fmaf(A2, pB, B2);
        }
        __syncthreads();
    }

    float h = (tid == 0) ? 0.f : cB[tid - 1];
#pragma unroll
    for (int j = 0; j < 16; j++) {
        int idx = j * 513 + tid;
        h = fmaf(sa[idx], h, sb[idx]);
        sa[idx] = h;
    }
    __syncthreads();

#pragma unroll 4
    for (int c2 = 0; c2 < 16; c2++) {
        int e = c2 * 512 + tid;
        int t = dir ? (LSEQ - 1 - e) : e;
        orow[t] = sa[(e & 15) * 513 + (e >> 4)];
    }
}

// ---------------------------------------------------------------------------
// Launch
// ---------------------------------------------------------------------------
extern "C" void kernel_launch(void* const* d_in, const int* in_sizes, int n_in,
                              void* d_out, int out_size)
{
    const float* x  = (const float*)d_in[0];
    const float* wf = (const float*)d_in[1];
    const float* bf = (const float*)d_in[2];
    const float* wb = (const float*)d_in[3];
    const float* bb = (const float*)d_in[4];
    float* out = (float*)d_out;

    cudaFuncSetAttribute(gemm_hmma2,
                         cudaFuncAttributeMaxDynamicSharedMemorySize,
                         3 * STAGE_BYTES);
    cudaFuncSetAttribute(mingru_scan3,
                         cudaFuncAttributeMaxDynamicSharedMemorySize, 65664);

    convert_w<<<512, 256>>>(wf, wb);
    convert_x<<<dim3(128, 8), 256>>>(x);

    gemm_hmma2<<<dim3(8, 512), 256, 3 * STAGE_BYTES>>>(bf, bb);

    mingru_scan3<<<4096, 512, 65664>>>(out);
}